// round 12
// baseline (speedup 1.0000x reference)
#include <cuda_runtime.h>

// HSE (hard-sigmoid squeeze-excitation) for x[64, 768, 28, 28] fp32.
// R10: cluster-per-batch. The whole dependency of s[b,:] is x[b] = 2.35 MB,
// which a 12-CTA cluster holds in SMEM (196 KB/CTA, 64 channels each).
// x is read from DRAM exactly ONCE: load -> pool -> (cluster.sync) ->
// mlp1 split by rank -> (cluster.sync) -> mlp2 -> scale SMEM copy -> store.
// DRAM traffic 462 MB -> 308 MB by construction (no L2-retention gamble).

#define BATCH    64
#define CH       768
#define HID      192
#define HW       784
#define VEC4     (HW / 4)          // 196 float4 per plane

#define NC       12                // CTAs per cluster (nonportable >8)
#define CPC      (CH / NC)         // 64 channels per CTA
#define THREADS  512
#define NW       (THREADS / 32)    // 16 warps

#define XS_F4    (CPC * VEC4)      // 12544 float4 in smem
#define SMEM_XS    0
#define SMEM_PF    (CPC * HW * 4)             // 200704: pooled_full[768]
#define SMEM_HF    (SMEM_PF + CH * 4)         // 203776: h_full[192]
#define SMEM_SV    (SMEM_HF + HID * 4)        // 204544: sv[64]
#define SMEM_TOTAL (SMEM_SV + CPC * 4)        // 204800

__device__ float g_pooled[BATCH * CH];
__device__ float g_h[BATCH * HID];

#define CLUSTER_SYNC() do {                                        \
    asm volatile("barrier.cluster.arrive.aligned;" ::: "memory");  \
    asm volatile("barrier.cluster.wait.aligned;"   ::: "memory");  \
} while (0)

__global__ __launch_bounds__(THREADS, 1) __cluster_dims__(NC, 1, 1)
void hse_kernel(const float4* __restrict__ x,
                const float4* __restrict__ w1,
                const float*  __restrict__ b1,
                const float2* __restrict__ w2,
                const float*  __restrict__ b2,
                float4*       __restrict__ out) {
    extern __shared__ __align__(16) char smem[];
    float4* xs = reinterpret_cast<float4*>(smem + SMEM_XS);
    float*  pf = reinterpret_cast<float*>(smem + SMEM_PF);
    float*  hf = reinterpret_cast<float*>(smem + SMEM_HF);
    float*  sv = reinterpret_cast<float*>(smem + SMEM_SV);

    const int t    = threadIdx.x;
    const int lane = t & 31;
    const int w    = t >> 5;
    const int batch = blockIdx.x / NC;
    const int rank  = blockIdx.x - batch * NC;
    const int c0    = rank * CPC;              // my first channel

    // ---- 1. load my 64 channel-planes DRAM -> SMEM (coalesced, once) ----
    const float4* xg = x + ((size_t)batch * CH + c0) * VEC4;
#pragma unroll 5
    for (int i = t; i < XS_F4; i += THREADS)
        xs[i] = xg[i];
    __syncthreads();

    // ---- 2. local pool: warp w handles planes w, w+16, w+32, w+48 ----
#pragma unroll
    for (int j = 0; j < CPC / NW; j++) {
        int p = w + NW * j;
        const float4* pp = xs + p * VEC4;
        float s = 0.0f;
#pragma unroll
        for (int i = 0; i < 6; i++) {
            float4 v = pp[lane + 32 * i];
            s += (v.x + v.y) + (v.z + v.w);
        }
        if (lane < 4) {
            float4 v = pp[192 + lane];
            s += (v.x + v.y) + (v.z + v.w);
        }
#pragma unroll
        for (int off = 16; off; off >>= 1)
            s += __shfl_xor_sync(0xffffffffu, s, off);
        if (lane == 0)
            g_pooled[batch * CH + c0 + p] = s * (1.0f / 784.0f);
    }

    // ---- 3. exchange pooled across the cluster ----
    CLUSTER_SYNC();
    for (int j = t; j < CH; j += THREADS)
        pf[j] = g_pooled[batch * CH + j];
    __syncthreads();

    // ---- 4. mlp1: my 16 rows of h (warp per row), w1 L2-hot ----
    {
        int r = rank * (HID / NC) + w;         // 16 warps, 16 rows
        const float4* wrow = w1 + (size_t)r * (CH / 4);
        const float4* pv   = reinterpret_cast<const float4*>(pf);
        float acc = 0.0f;
#pragma unroll
        for (int i = 0; i < 6; i++) {
            float4 wv = wrow[lane + 32 * i];
            float4 p  = pv[lane + 32 * i];
            acc += wv.x * p.x + wv.y * p.y + wv.z * p.z + wv.w * p.w;
        }
#pragma unroll
        for (int off = 16; off; off >>= 1)
            acc += __shfl_xor_sync(0xffffffffu, acc, off);
        if (lane == 0)
            g_h[batch * HID + r] = fmaxf(acc + b1[r], 0.0f);
    }

    // ---- 5. exchange h across the cluster ----
    CLUSTER_SYNC();
    if (t < HID) hf[t] = g_h[batch * HID + t];
    __syncthreads();

    // ---- 6. mlp2: my 64 channels' scales (warp per channel, 4 rounds) ----
    const float2* hv = reinterpret_cast<const float2*>(hf);
#pragma unroll
    for (int j = 0; j < CPC / NW; j++) {
        int cl = w + NW * j;                   // local channel
        int c  = c0 + cl;
        const float2* wrow = w2 + (size_t)c * (HID / 2);
        float acc = 0.0f;
#pragma unroll
        for (int i = 0; i < 3; i++) {
            float2 wv = wrow[lane + 32 * i];
            float2 h  = hv[lane + 32 * i];
            acc += wv.x * h.x + wv.y * h.y;
        }
#pragma unroll
        for (int off = 16; off; off >>= 1)
            acc += __shfl_xor_sync(0xffffffffu, acc, off);
        if (lane == 0)
            sv[cl] = __saturatef(fmaf(acc + b2[c], 1.0f / 6.0f, 0.5f));
    }
    __syncthreads();

    // ---- 7. scale the SMEM copy and stream out (read x ZERO extra times) ----
    float4* og = out + ((size_t)batch * CH + c0) * VEC4;
#pragma unroll 5
    for (int i = t; i < XS_F4; i += THREADS) {
        float s = sv[i / VEC4];
        float4 v = xs[i];
        v.x *= s; v.y *= s; v.z *= s; v.w *= s;
        __stcs(&og[i], v);
    }
}

// ---------------------------------------------------------------------------
extern "C" void kernel_launch(void* const* d_in, const int* in_sizes, int n_in,
                              void* d_out, int out_size) {
    const float4* x  = (const float4*)d_in[0];
    const float4* w1 = (const float4*)d_in[1];
    const float*  b1 = (const float*)d_in[2];
    const float2* w2 = (const float2*)d_in[3];
    const float*  b2 = (const float*)d_in[4];
    float4* out = (float4*)d_out;

    static int configured = 0;
    if (!configured) {
        cudaFuncSetAttribute(hse_kernel,
                             cudaFuncAttributeMaxDynamicSharedMemorySize,
                             SMEM_TOTAL);
        cudaFuncSetAttribute(hse_kernel,
                             cudaFuncAttributeNonPortableClusterSizeAllowed, 1);
        configured = 1;
    }

    hse_kernel<<<BATCH * NC, THREADS, SMEM_TOTAL>>>(x, w1, b1, w2, b2, out);
}

// round 16
// speedup vs baseline: 1.1061x; 1.1061x over previous
#include <cuda_runtime.h>

// HSE (hard-sigmoid squeeze-excitation) for x[64, 768, 28, 28] fp32.
// R15 = R14 with the smem-overflow fix: sv_s needs up to 333 floats (1332 B)
// but only 512 B were reserved -> illegal memory access. Now 1408 B.
//
// Design: persistent 148-CTA kernel, 1 CTA/SM (200KB smem -> occ=1, all CTAs
// co-resident on the 152-SM chip; two single-atomic grid barriers, reset by
// init_kernel each replay). Each CTA owns ~332 contiguous planes: 64 in SMEM,
// the rest read once into L2 (125 MB fits the 126 MB L2; __stwt stores never
// allocate, __ldcs smem-fill is evict-first). DRAM traffic ~= 154 read +
// 154 write + small misses, vs 462 MB for the 3-pass design (78.6us).

#define BATCH    64
#define CH       768
#define HID      192
#define HW       784
#define PLANES   (BATCH * CH)        // 49152
#define VEC4     (HW / 4)            // 196

#define NCTA     148
#define THREADS  1024
#define SPLANES  64                  // planes held in SMEM per CTA
#define SMEM_X   (SPLANES * VEC4)    // 12544 float4 = 200704 B
#define SV_FLOATS 352                // >= max cnt (333), padded
#define SMEM_BYTES (SMEM_X * 16 + SV_FLOATS * 4)   // 202112 < 227KB cap
// chunk: first 16 CTAs get 333 planes, rest 332  (16*333 + 132*332 = 49152)
#define BASEP    332

__device__ float g_pooled[PLANES];
__device__ float g_h[BATCH * HID];
__device__ int   g_bar1, g_bar2;

__global__ void init_kernel() {
    if (threadIdx.x == 0) { g_bar1 = 0; g_bar2 = 0; }
}

__device__ __forceinline__ void grid_barrier(int* bar) {
    __syncthreads();
    if (threadIdx.x == 0) {
        __threadfence();
        atomicAdd(bar, 1);
        while (*(volatile int*)bar < NCTA) __nanosleep(64);
        __threadfence();
    }
    __syncthreads();
}

__device__ __forceinline__ float plane_sum(const float4* __restrict__ p, int lane) {
    float s = 0.0f;
#pragma unroll
    for (int i = 0; i < 6; i++) {
        float4 v = p[lane + 32 * i];
        s += (v.x + v.y) + (v.z + v.w);
    }
    if (lane < 4) {
        float4 v = p[192 + lane];
        s += (v.x + v.y) + (v.z + v.w);
    }
#pragma unroll
    for (int off = 16; off; off >>= 1)
        s += __shfl_xor_sync(0xffffffffu, s, off);
    return s;
}

__global__ __launch_bounds__(THREADS, 1)
void hse_kernel(const float4* __restrict__ x,
                const float4* __restrict__ w1,
                const float*  __restrict__ b1,
                const float2* __restrict__ w2,
                const float*  __restrict__ b2,
                float4*       __restrict__ out) {
    extern __shared__ __align__(16) char smem[];
    float4* xs   = reinterpret_cast<float4*>(smem);
    float*  sv_s = reinterpret_cast<float*>(smem + SMEM_X * 16);   // [SV_FLOATS]

    const int t    = threadIdx.x;
    const int lane = t & 31;
    const int w    = t >> 5;                  // 0..31
    const int cta  = blockIdx.x;
    const int start = cta * BASEP + (cta < 16 ? cta : 16);
    const int cnt   = BASEP + (cta < 16 ? 1 : 0);

    const float4* xg = x + (size_t)start * VEC4;

    // ---- phase A1: SMEM planes DRAM->SMEM (evict-first in L2: copy lives here)
#pragma unroll 4
    for (int i = t; i < SMEM_X; i += THREADS)
        xs[i] = __ldcs(&xg[i]);

    // ---- phase A2: pool the non-SMEM planes (2 adjacent planes per warp pass;
    //      default policy -> lines stay L2-resident for phase B)
    for (int p = SPLANES + 2 * w; p < cnt; p += 2 * 32) {
        if (p + 1 < cnt) {
            const float4* p0 = xg + (size_t)p * VEC4;
            const float4* p1 = p0 + VEC4;
            float s0 = 0.0f, s1 = 0.0f;
#pragma unroll
            for (int i = 0; i < 6; i++) {
                float4 a = p0[lane + 32 * i];
                float4 b = p1[lane + 32 * i];
                s0 += (a.x + a.y) + (a.z + a.w);
                s1 += (b.x + b.y) + (b.z + b.w);
            }
            if (lane < 4) {
                float4 a = p0[192 + lane];
                float4 b = p1[192 + lane];
                s0 += (a.x + a.y) + (a.z + a.w);
                s1 += (b.x + b.y) + (b.z + b.w);
            }
#pragma unroll
            for (int off = 16; off; off >>= 1) {
                s0 += __shfl_xor_sync(0xffffffffu, s0, off);
                s1 += __shfl_xor_sync(0xffffffffu, s1, off);
            }
            if (lane == 0) {
                g_pooled[start + p]     = s0 * (1.0f / 784.0f);
                g_pooled[start + p + 1] = s1 * (1.0f / 784.0f);
            }
        } else {
            float s0 = plane_sum(xg + (size_t)p * VEC4, lane);
            if (lane == 0) g_pooled[start + p] = s0 * (1.0f / 784.0f);
        }
    }
    __syncthreads();

    // ---- phase A3: pool the SMEM planes (from smem, cheap)
#pragma unroll
    for (int j = 0; j < SPLANES / 32; j++) {
        int p = w + 32 * j;
        float s = plane_sum(xs + p * VEC4, lane);
        if (lane == 0) g_pooled[start + p] = s * (1.0f / 784.0f);
    }

    grid_barrier(&g_bar1);

    // ---- phase M: h = relu(w1 @ pooled + b1), warp-per-(b,r) over the grid
    {
        int gw = cta * 32 + w;                       // 0..4735
        for (int task = gw; task < BATCH * HID; task += NCTA * 32) {
            int b = task / HID;
            int r = task - b * HID;
            const float4* wrow = w1 + (size_t)r * (CH / 4);
            const float4* pv   = reinterpret_cast<const float4*>(g_pooled) + b * (CH / 4);
            float acc = 0.0f;
#pragma unroll
            for (int i = 0; i < 6; i++) {
                float4 wv = wrow[lane + 32 * i];
                float4 p  = __ldcg(&pv[lane + 32 * i]);
                acc += wv.x * p.x + wv.y * p.y + wv.z * p.z + wv.w * p.w;
            }
#pragma unroll
            for (int off = 16; off; off >>= 1)
                acc += __shfl_xor_sync(0xffffffffu, acc, off);
            if (lane == 0) g_h[b * HID + r] = fmaxf(acc + b1[r], 0.0f);
        }
    }

    grid_barrier(&g_bar2);

    // ---- phase S: s for my planes (warp per plane) -> smem sv_s
    for (int p = w; p < cnt; p += 32) {
        int plane = start + p;
        int b = plane / CH;
        int c = plane - b * CH;
        const float2* wrow = w2 + (size_t)c * (HID / 2);
        const float2* hv   = reinterpret_cast<const float2*>(g_h) + b * (HID / 2);
        float acc = 0.0f;
#pragma unroll
        for (int i = 0; i < 3; i++) {
            float2 wv = wrow[lane + 32 * i];
            float2 h  = __ldcg(&hv[lane + 32 * i]);
            acc += wv.x * h.x + wv.y * h.y;
        }
#pragma unroll
        for (int off = 16; off; off >>= 1)
            acc += __shfl_xor_sync(0xffffffffu, acc, off);
        if (lane == 0)
            sv_s[p] = __saturatef(fmaf(acc + b2[c], 1.0f / 6.0f, 0.5f));
    }
    __syncthreads();

    // ---- phase B: stream out = x * s. SMEM part from smem, rest from L2.
    float4* og = out + (size_t)start * VEC4;
#pragma unroll 4
    for (int i = t; i < SMEM_X; i += THREADS) {
        float s = sv_s[i / VEC4];
        float4 v = xs[i];
        v.x *= s; v.y *= s; v.z *= s; v.w *= s;
        __stwt(&og[i], v);
    }
    const int tot = cnt * VEC4;
#pragma unroll 4
    for (int i = SMEM_X + t; i < tot; i += THREADS) {
        float s = sv_s[i / VEC4];
        float4 v = __ldcs(&xg[i]);      // L2-resident from phase A2; dead after
        v.x *= s; v.y *= s; v.z *= s; v.w *= s;
        __stwt(&og[i], v);
    }
}

// ---------------------------------------------------------------------------
extern "C" void kernel_launch(void* const* d_in, const int* in_sizes, int n_in,
                              void* d_out, int out_size) {
    const float4* x  = (const float4*)d_in[0];
    const float4* w1 = (const float4*)d_in[1];
    const float*  b1 = (const float*)d_in[2];
    const float2* w2 = (const float2*)d_in[3];
    const float*  b2 = (const float*)d_in[4];
    float4* out = (float4*)d_out;

    cudaFuncSetAttribute(hse_kernel,
                         cudaFuncAttributeMaxDynamicSharedMemorySize,
                         SMEM_BYTES);

    init_kernel<<<1, 32>>>();
    hse_kernel<<<NCTA, THREADS, SMEM_BYTES>>>(x, w1, b1, w2, b2, out);
}

// round 17
// speedup vs baseline: 1.3697x; 1.2383x over previous
#include <cuda_runtime.h>

// HSE (hard-sigmoid squeeze-excitation) for x[64, 768, 28, 28] fp32.
// R16: persistent fused kernel, occupancy-first. R15 proved the traffic cut
// (375 MB vs 462) but ran at 46.8% DRAM because 64 regs + 200KB smem capped
// the SM at 32 warps. This version: no smem x-stage, <=32 regs via
// __launch_bounds__(256,8) -> 64 warps/SM, 1024 co-resident CTAs (128 SMs).
// Phase A pools x (normal policy -> L2 fill). Phase B re-reads in REVERSE
// (most-recent-first beats LRU thrash), __ldcs (dead after use) + __stwt
// stores (no L2 allocation -> cannot evict x). Expected DRAM ~= 340 MB.

#define BATCH    64
#define CH       768
#define HID      192
#define HW       784
#define PLANES   (BATCH * CH)        // 49152
#define VEC4     (HW / 4)            // 196

#define NCTA     1024
#define THREADS  256
#define PPC      (PLANES / NCTA)     // 48 planes per CTA
#define PF4      (PPC * VEC4)        // 9408 float4 per CTA

__device__ float g_pooled[PLANES];
__device__ float g_h[BATCH * HID];
__device__ int   g_bar1, g_bar2;

__global__ void init_kernel() {
    if (threadIdx.x == 0) { g_bar1 = 0; g_bar2 = 0; }
}

__device__ __forceinline__ void grid_barrier(int* bar) {
    __syncthreads();
    if (threadIdx.x == 0) {
        __threadfence();
        atomicAdd(bar, 1);
        while (*(volatile int*)bar < NCTA) __nanosleep(64);
        __threadfence();
    }
    __syncthreads();
}

__device__ __forceinline__ float plane_sum(const float4* __restrict__ p, int lane) {
    float s = 0.0f;
#pragma unroll
    for (int i = 0; i < 6; i++) {
        float4 v = p[lane + 32 * i];
        s += (v.x + v.y) + (v.z + v.w);
    }
    if (lane < 4) {
        float4 v = p[192 + lane];
        s += (v.x + v.y) + (v.z + v.w);
    }
#pragma unroll
    for (int off = 16; off; off >>= 1)
        s += __shfl_xor_sync(0xffffffffu, s, off);
    return s;
}

__global__ __launch_bounds__(THREADS, 8)
void hse_kernel(const float4* __restrict__ x,
                const float4* __restrict__ w1,
                const float*  __restrict__ b1,
                const float2* __restrict__ w2,
                const float*  __restrict__ b2,
                float4*       __restrict__ out) {
    __shared__ float sv_s[PPC];

    const int t    = threadIdx.x;
    const int lane = t & 31;
    const int wid  = t >> 5;                  // 0..7
    const int cta  = blockIdx.x;
    const int start = cta * PPC;

    const float4* xg = x + (size_t)start * VEC4;

    // ---- phase A: pool my 48 planes (normal policy: x fills L2) ----
    for (int p = wid; p < PPC; p += 8) {
        float s = plane_sum(xg + (size_t)p * VEC4, lane);
        if (lane == 0) g_pooled[start + p] = s * (1.0f / 784.0f);
    }

    grid_barrier(&g_bar1);

    // ---- phase M: h = relu(w1 @ pooled + b1), warp-per-(b,r) ----
    {
        int gw = cta * 8 + wid;                     // 0..8191
        for (int task = gw; task < BATCH * HID; task += NCTA * 8) {
            int b = task / HID;
            int r = task - b * HID;
            const float4* wrow = w1 + (size_t)r * (CH / 4);
            const float4* pv   = reinterpret_cast<const float4*>(g_pooled) + b * (CH / 4);
            float acc = 0.0f;
#pragma unroll
            for (int i = 0; i < 6; i++) {
                float4 wv = wrow[lane + 32 * i];
                float4 p  = __ldcg(&pv[lane + 32 * i]);
                acc += wv.x * p.x + wv.y * p.y + wv.z * p.z + wv.w * p.w;
            }
#pragma unroll
            for (int off = 16; off; off >>= 1)
                acc += __shfl_xor_sync(0xffffffffu, acc, off);
            if (lane == 0) g_h[b * HID + r] = fmaxf(acc + b1[r], 0.0f);
        }
    }

    grid_barrier(&g_bar2);

    // ---- phase S: scales for my planes -> smem ----
    for (int p = wid; p < PPC; p += 8) {
        int plane = start + p;
        int b = plane / CH;
        int c = plane - b * CH;
        const float2* wrow = w2 + (size_t)c * (HID / 2);
        const float2* hv   = reinterpret_cast<const float2*>(g_h) + b * (HID / 2);
        float acc = 0.0f;
#pragma unroll
        for (int i = 0; i < 3; i++) {
            float2 wv = wrow[lane + 32 * i];
            float2 h  = __ldcg(&hv[lane + 32 * i]);
            acc += wv.x * h.x + wv.y * h.y;
        }
#pragma unroll
        for (int off = 16; off; off >>= 1)
            acc += __shfl_xor_sync(0xffffffffu, acc, off);
        if (lane == 0)
            sv_s[p] = __saturatef(fmaf(acc + b2[c], 1.0f / 6.0f, 0.5f));
    }
    __syncthreads();

    // ---- phase B: out = x * s, REVERSE order (most-recent L2 lines first).
    //      __ldcs: line dead after read. __stwt: store never allocates.
    float4* og = out + (size_t)start * VEC4;
    for (int i = PF4 - THREADS + t; i >= 0; i -= THREADS) {
        float s = sv_s[i / VEC4];
        float4 v = __ldcs(&xg[i]);
        v.x *= s; v.y *= s; v.z *= s; v.w *= s;
        __stwt(&og[i], v);
    }
}

// ---------------------------------------------------------------------------
extern "C" void kernel_launch(void* const* d_in, const int* in_sizes, int n_in,
                              void* d_out, int out_size) {
    const float4* x  = (const float4*)d_in[0];
    const float4* w1 = (const float4*)d_in[1];
    const float*  b1 = (const float*)d_in[2];
    const float2* w2 = (const float2*)d_in[3];
    const float*  b2 = (const float*)d_in[4];
    float4* out = (float4*)d_out;

    init_kernel<<<1, 32>>>();
    hse_kernel<<<NCTA, THREADS>>>(x, w1, b1, w2, b2, out);
}